// round 1
// baseline (speedup 1.0000x reference)
#include <cuda_runtime.h>
#include <math_constants.h>

#define BB   2
#define TT   2048
#define CC   2048
#define NH   16
#define NKV  4
#define HD   128
#define GC   32
#define MTOK (BB*TT)

#define BR 64
#define BC 32
#define KP (HD+4)

// ---------------- scratch (device globals: no allocations allowed) ----------
__device__ float g_q[(size_t)MTOK*NH*HD];
__device__ float g_k[(size_t)MTOK*NKV*HD];
__device__ float g_v[(size_t)MTOK*NKV*HD];
__device__ float g_y[(size_t)MTOK*CC];

// ---------------- SGEMM: C[M,N] = A[M,K] @ B[K,N], 128x128x8, 256 thr -------
__global__ __launch_bounds__(256) void sgemm_kernel(
    const float* __restrict__ A, const float* __restrict__ Bm,
    float* __restrict__ Cm, int M, int N, int K)
{
    __shared__ float As[8][128];
    __shared__ float Bs[8][128];
    const int tid  = threadIdx.x;
    const int bm   = blockIdx.y * 128;
    const int bn   = blockIdx.x * 128;
    const int arow = tid >> 1;
    const int acol = (tid & 1) << 2;
    const int brow = tid >> 5;
    const int bcol = (tid & 31) << 2;
    const int tx   = (tid & 15) << 3;
    const int ty   = (tid >> 4) << 3;

    float acc[8][8];
#pragma unroll
    for (int i = 0; i < 8; i++)
#pragma unroll
        for (int j = 0; j < 8; j++) acc[i][j] = 0.f;

    const float* Aptr = A  + (size_t)(bm + arow) * K + acol;
    const float* Bptr = Bm + (size_t)brow * N + bn + bcol;

    for (int k0 = 0; k0 < K; k0 += 8) {
        float4 av = *(const float4*)(Aptr + k0);
        As[acol + 0][arow] = av.x;
        As[acol + 1][arow] = av.y;
        As[acol + 2][arow] = av.z;
        As[acol + 3][arow] = av.w;
        *(float4*)&Bs[brow][bcol] = *(const float4*)(Bptr + (size_t)k0 * N);
        __syncthreads();
#pragma unroll
        for (int k = 0; k < 8; k++) {
            float a[8], b[8];
            *(float4*)(a)     = *(float4*)&As[k][ty];
            *(float4*)(a + 4) = *(float4*)&As[k][ty + 4];
            *(float4*)(b)     = *(float4*)&Bs[k][tx];
            *(float4*)(b + 4) = *(float4*)&Bs[k][tx + 4];
#pragma unroll
            for (int i = 0; i < 8; i++)
#pragma unroll
                for (int j = 0; j < 8; j++) acc[i][j] += a[i] * b[j];
        }
        __syncthreads();
    }
#pragma unroll
    for (int i = 0; i < 8; i++) {
        float* cp = Cm + (size_t)(bm + ty + i) * N + bn + tx;
        *(float4*)(cp)     = make_float4(acc[i][0], acc[i][1], acc[i][2], acc[i][3]);
        *(float4*)(cp + 4) = make_float4(acc[i][4], acc[i][5], acc[i][6], acc[i][7]);
    }
}

// ---------------- QKV epilogue: gate+ve add, RoPE + RMS on q,k --------------
__global__ __launch_bounds__(256) void qkv_epilogue(
    float* __restrict__ q, float* __restrict__ k, float* __restrict__ v,
    const float* __restrict__ x, const float* __restrict__ ve,
    const float* __restrict__ cosb, const float* __restrict__ sinb,
    const float* __restrict__ Wgate)
{
    const int token = blockIdx.x;
    const int t     = token & (TT - 1);
    const int tid   = threadIdx.x;

    __shared__ float gate[NKV];
    if (tid < NKV) {
        float s = 0.f;
        const float* xp = x + (size_t)token * CC;
#pragma unroll
        for (int g = 0; g < GC; g++) s += xp[g] * Wgate[g * NKV + tid];
        gate[tid] = 2.f / (1.f + expf(-s));
    }
    __syncthreads();

    {   // v = v + gate * ve
        float* vp        = v  + (size_t)token * (NKV * HD);
        const float* vep = ve + (size_t)token * (NKV * HD);
        for (int i = tid; i < NKV * HD; i += 256)
            vp[i] += gate[i >> 7] * vep[i];
    }

    const int warp = tid >> 5, lane = tid & 31;
    const float* cp = cosb + (size_t)t * (HD / 2);
    const float* sp = sinb + (size_t)t * (HD / 2);
    for (int h = warp; h < NH + NKV; h += 8) {
        float* base = (h < NH) ? (q + (size_t)token * (NH * HD) + h * HD)
                               : (k + (size_t)token * (NKV * HD) + (h - NH) * HD);
        float t1a = base[lane],      t2a = base[lane + 64];
        float t1b = base[lane + 32], t2b = base[lane + 96];
        float ca = cp[lane],      sa = sp[lane];
        float cb = cp[lane + 32], sb = sp[lane + 32];
        float o0 =  t1a * ca + t2a * sa;
        float o1 = -t1a * sa + t2a * ca;
        float o2 =  t1b * cb + t2b * sb;
        float o3 = -t1b * sb + t2b * cb;
        float ss = o0 * o0 + o1 * o1 + o2 * o2 + o3 * o3;
#pragma unroll
        for (int off = 16; off; off >>= 1)
            ss += __shfl_xor_sync(0xffffffffu, ss, off);
        float sc = rsqrtf(ss * (1.f / HD) + 1.19209290e-07f);
        base[lane]      = o0 * sc;
        base[lane + 64] = o1 * sc;
        base[lane + 32] = o2 * sc;
        base[lane + 96] = o3 * sc;
    }
}

// ---------------- Flash attention (fp32 SIMT, online softmax) ---------------
// grid: (T/BR, NH, B); block 256 = 8 warps; warp w owns q-rows [q0+8w, q0+8w+8)
// lane j owns key-column (tile*32+j) for scores, and d = 4*lane..4*lane+3 for acc.
__global__ __launch_bounds__(256) void attn_kernel(
    const float* __restrict__ q, const float* __restrict__ k,
    const float* __restrict__ v, float* __restrict__ y)
{
    extern __shared__ float sm[];
    float* Qs = sm;                   // BR * KP
    float* Ks = Qs + BR * KP;         // BC * KP
    float* Vs = Ks + BC * KP;         // BC * KP

    const int q0   = blockIdx.x * BR;
    const int h    = blockIdx.y;
    const int b    = blockIdx.z;
    const int hk   = h >> 2;          // NH/NKV = 4
    const int tid  = threadIdx.x;
    const int warp = tid >> 5, lane = tid & 31;

    const float qscale = 0.08838834764831845f;  // 1/sqrt(HD)

    for (int i = tid; i < BR * (HD / 4); i += 256) {
        int r  = i >> 5;
        int dq = (i & 31) << 2;
        float4 qv = *(const float4*)(q + ((size_t)(b * TT + q0 + r) * NH + h) * HD + dq);
        qv.x *= qscale; qv.y *= qscale; qv.z *= qscale; qv.w *= qscale;
        *(float4*)&Qs[r * KP + dq] = qv;
    }

    const int r0 = warp * 8;
    float m[8], l[8], acc[8][4];
#pragma unroll
    for (int r = 0; r < 8; r++) {
        m[r] = -CUDART_INF_F; l[r] = 0.f;
        acc[r][0] = acc[r][1] = acc[r][2] = acc[r][3] = 0.f;
    }

    const int ntiles = (q0 + BR) / BC;
    for (int jt = 0; jt < ntiles; jt++) {
        __syncthreads();   // K/V reuse guard (iter 0: also orders Q load)
        for (int i = tid; i < BC * (HD / 4); i += 256) {
            int r  = i >> 5;
            int dq = (i & 31) << 2;
            int kk = jt * BC + r;
            const size_t g = ((size_t)(b * TT + kk) * NKV + hk) * HD + dq;
            *(float4*)&Ks[r * KP + dq] = *(const float4*)(k + g);
            *(float4*)&Vs[r * KP + dq] = *(const float4*)(v + g);
        }
        __syncthreads();

        float s[8];
#pragma unroll
        for (int r = 0; r < 8; r++) s[r] = 0.f;
#pragma unroll 8
        for (int d = 0; d < HD; d += 4) {
            float4 kv = *(float4*)&Ks[lane * KP + d];
#pragma unroll
            for (int r = 0; r < 8; r++) {
                float4 qv = *(float4*)&Qs[(r0 + r) * KP + d];
                s[r] += qv.x * kv.x + qv.y * kv.y + qv.z * kv.z + qv.w * kv.w;
            }
        }

        const int kcol = jt * BC + lane;
#pragma unroll
        for (int r = 0; r < 8; r++) {
            const int qrow = q0 + r0 + r;
            float sv = (kcol <= qrow) ? s[r] : -CUDART_INF_F;
            float mt = sv;
#pragma unroll
            for (int off = 16; off; off >>= 1)
                mt = fmaxf(mt, __shfl_xor_sync(0xffffffffu, mt, off));
            float mnew  = fmaxf(m[r], mt);
            float alpha = __expf(m[r] - mnew);   // m=-inf first tile -> 0
            float p     = __expf(sv - mnew);
            float lt = p;
#pragma unroll
            for (int off = 16; off; off >>= 1)
                lt += __shfl_xor_sync(0xffffffffu, lt, off);
            l[r] = l[r] * alpha + lt;
            m[r] = mnew;
            acc[r][0] *= alpha; acc[r][1] *= alpha;
            acc[r][2] *= alpha; acc[r][3] *= alpha;
            s[r] = p;
        }

#pragma unroll
        for (int j = 0; j < BC; j++) {
            float4 vv = *(float4*)&Vs[j * KP + (lane << 2)];
#pragma unroll
            for (int r = 0; r < 8; r++) {
                float pj = __shfl_sync(0xffffffffu, s[r], j);
                acc[r][0] += pj * vv.x;
                acc[r][1] += pj * vv.y;
                acc[r][2] += pj * vv.z;
                acc[r][3] += pj * vv.w;
            }
        }
    }

#pragma unroll
    for (int r = 0; r < 8; r++) {
        float inv = 1.f / l[r];
        float4 o = make_float4(acc[r][0] * inv, acc[r][1] * inv,
                               acc[r][2] * inv, acc[r][3] * inv);
        *(float4*)(y + (size_t)(b * TT + q0 + r0 + r) * CC + h * HD + (lane << 2)) = o;
    }
}

// ---------------- launch ----------------------------------------------------
extern "C" void kernel_launch(void* const* d_in, const int* in_sizes, int n_in,
                              void* d_out, int out_size)
{
    const float* x     = (const float*)d_in[0];
    const float* ve    = (const float*)d_in[1];
    const float* cosb  = (const float*)d_in[2];
    const float* sinb  = (const float*)d_in[3];
    const float* Wq    = (const float*)d_in[4];
    const float* Wk    = (const float*)d_in[5];
    const float* Wv    = (const float*)d_in[6];
    const float* Wproj = (const float*)d_in[7];
    const float* Wgate = (const float*)d_in[8];
    float* out = (float*)d_out;

    float *qb, *kb, *vb, *yb;
    cudaGetSymbolAddress((void**)&qb, g_q);
    cudaGetSymbolAddress((void**)&kb, g_k);
    cudaGetSymbolAddress((void**)&vb, g_v);
    cudaGetSymbolAddress((void**)&yb, g_y);

    dim3 blk(256);
    sgemm_kernel<<<dim3((NH * HD) / 128, MTOK / 128), blk>>>(x, Wq, qb, MTOK, NH * HD, CC);
    sgemm_kernel<<<dim3((NKV * HD) / 128, MTOK / 128), blk>>>(x, Wk, kb, MTOK, NKV * HD, CC);
    sgemm_kernel<<<dim3((NKV * HD) / 128, MTOK / 128), blk>>>(x, Wv, vb, MTOK, NKV * HD, CC);

    qkv_epilogue<<<MTOK, 256>>>(qb, kb, vb, x, ve, cosb, sinb, Wgate);

    const int smem = (BR * KP + 2 * BC * KP) * (int)sizeof(float);
    cudaFuncSetAttribute(attn_kernel, cudaFuncAttributeMaxDynamicSharedMemorySize, smem);
    attn_kernel<<<dim3(TT / BR, NH, BB), 256, smem>>>(qb, kb, vb, yb);

    sgemm_kernel<<<dim3(CC / 128, MTOK / 128), blk>>>(yb, Wproj, out, MTOK, CC, CC);
}

// round 2
// speedup vs baseline: 1.5949x; 1.5949x over previous
#include <cuda_runtime.h>
#include <cuda_bf16.h>
#include <math_constants.h>

#define BB   2
#define TT   2048
#define CC   2048
#define NH   16
#define NKV  4
#define HD   128
#define GC   32
#define MTOK (BB*TT)

#define BR 64
#define BC 32
#define KP (HD+4)

// ---------------- scratch (device globals: no allocations allowed) ----------
__device__ float g_q[(size_t)MTOK*NH*HD];
__device__ float g_k[(size_t)MTOK*NKV*HD];
__device__ float g_v[(size_t)MTOK*NKV*HD];
__device__ float g_y[(size_t)MTOK*CC];

// ======================= bf16x3 tensor-core GEMM ============================
// C[M,N] = A[M,K] @ B[K,N], fp32 in/out, bf16 split (hi+lo) on tensor cores.
// Error ~2^-17 (lo*lo term dropped). Block 128x128x32, 8 warps of 64x32.
#define GBM 128
#define GBN 128
#define GBK 32
#define AKP 40    // A smem k-stride in bf16 elems (80B rows: ldmatrix conflict-free)
#define BNP 136   // B smem n-stride in bf16 elems (272B rows)

__device__ __forceinline__ unsigned smem_u32(const void* p) {
    return (unsigned)__cvta_generic_to_shared(p);
}

__device__ __forceinline__ void bsplit(float f, __nv_bfloat16& h, __nv_bfloat16& l) {
    h = __float2bfloat16(f);
    l = __float2bfloat16(f - __bfloat162float(h));
}

#define MMA16816(d, a, b0v, b1v)                                              \
    asm volatile("mma.sync.aligned.m16n8k16.row.col.f32.bf16.bf16.f32 "       \
                 "{%0,%1,%2,%3}, {%4,%5,%6,%7}, {%8,%9}, {%0,%1,%2,%3};"      \
                 : "+f"(d[0]), "+f"(d[1]), "+f"(d[2]), "+f"(d[3])             \
                 : "r"(a[0]), "r"(a[1]), "r"(a[2]), "r"(a[3]),                \
                   "r"(b0v), "r"(b1v))

#define LDSM_X4(r, addr)                                                      \
    asm volatile("ldmatrix.sync.aligned.m8n8.x4.shared.b16 {%0,%1,%2,%3}, [%4];" \
                 : "=r"(r[0]), "=r"(r[1]), "=r"(r[2]), "=r"(r[3]) : "r"(addr))

#define LDSM_X4T(r0, r1, r2, r3, addr)                                        \
    asm volatile("ldmatrix.sync.aligned.m8n8.x4.trans.shared.b16 {%0,%1,%2,%3}, [%4];" \
                 : "=r"(r0), "=r"(r1), "=r"(r2), "=r"(r3) : "r"(addr))

__global__ __launch_bounds__(256) void gemm_bf16x3(
    const float* __restrict__ A, const float* __restrict__ B,
    float* __restrict__ C, int M, int N, int K)
{
    __shared__ __nv_bfloat16 Ah[GBM * AKP], Al[GBM * AKP];
    __shared__ __nv_bfloat16 Bh[GBK * BNP], Bl[GBK * BNP];

    const int tid  = threadIdx.x;
    const int lane = tid & 31, warp = tid >> 5;
    const int wm   = warp >> 2, wn = warp & 3;          // 2 x 4 warp grid
    const int bm   = blockIdx.y * GBM, bn = blockIdx.x * GBN;
    const int li   = lane & 7;
    const int g1   = (lane >> 3) & 1;                    // +8 row selector
    const int g2   = lane >> 4;                          // +8 col selector

    float acc[4][4][4];
#pragma unroll
    for (int mt = 0; mt < 4; mt++)
#pragma unroll
        for (int nt = 0; nt < 4; nt++)
#pragma unroll
            for (int i = 0; i < 4; i++) acc[mt][nt][i] = 0.f;

    const int arow_l = tid >> 3;            // 0..31 (4 passes of 32 rows)
    const int acol_l = (tid & 7) << 2;      // 0,4,...,28
    const int brow_l = tid >> 5;            // 0..7  (4 passes of 8 rows)
    const int bcol_l = lane << 2;           // 0..124

    for (int k0 = 0; k0 < K; k0 += GBK) {
        // ---- stage A tile [128 x 32] fp32 -> bf16 hi/lo smem ----
#pragma unroll
        for (int p = 0; p < 4; p++) {
            int r = arow_l + 32 * p;
            float4 v = *(const float4*)(A + (size_t)(bm + r) * K + k0 + acol_l);
            __nv_bfloat16 h0, l0, h1, l1, h2, l2, h3, l3;
            bsplit(v.x, h0, l0); bsplit(v.y, h1, l1);
            bsplit(v.z, h2, l2); bsplit(v.w, h3, l3);
            int o = r * AKP + acol_l;
            *(__nv_bfloat162*)&Ah[o]     = __halves2bfloat162(h0, h1);
            *(__nv_bfloat162*)&Ah[o + 2] = __halves2bfloat162(h2, h3);
            *(__nv_bfloat162*)&Al[o]     = __halves2bfloat162(l0, l1);
            *(__nv_bfloat162*)&Al[o + 2] = __halves2bfloat162(l2, l3);
        }
        // ---- stage B tile [32 x 128] fp32 -> bf16 hi/lo smem ----
#pragma unroll
        for (int p = 0; p < 4; p++) {
            int kr = brow_l + 8 * p;
            float4 v = *(const float4*)(B + (size_t)(k0 + kr) * N + bn + bcol_l);
            __nv_bfloat16 h0, l0, h1, l1, h2, l2, h3, l3;
            bsplit(v.x, h0, l0); bsplit(v.y, h1, l1);
            bsplit(v.z, h2, l2); bsplit(v.w, h3, l3);
            int o = kr * BNP + bcol_l;
            *(__nv_bfloat162*)&Bh[o]     = __halves2bfloat162(h0, h1);
            *(__nv_bfloat162*)&Bh[o + 2] = __halves2bfloat162(h2, h3);
            *(__nv_bfloat162*)&Bl[o]     = __halves2bfloat162(l0, l1);
            *(__nv_bfloat162*)&Bl[o + 2] = __halves2bfloat162(l2, l3);
        }
        __syncthreads();

#pragma unroll
        for (int ks = 0; ks < 2; ks++) {
            // ---- B fragments for all 4 n-tiles (hi and lo) ----
            unsigned bh[8], bl[8];
#pragma unroll
            for (int pr = 0; pr < 2; pr++) {
                int krow = ks * 16 + g1 * 8 + li;
                int ncol = wn * 32 + pr * 16 + g2 * 8;
                unsigned ad = smem_u32(&Bh[krow * BNP + ncol]);
                LDSM_X4T(bh[4 * pr], bh[4 * pr + 1], bh[4 * pr + 2], bh[4 * pr + 3], ad);
                ad = smem_u32(&Bl[krow * BNP + ncol]);
                LDSM_X4T(bl[4 * pr], bl[4 * pr + 1], bl[4 * pr + 2], bl[4 * pr + 3], ad);
            }
            // ---- per m-tile: A fragments, then 3-pass mma over n-tiles ----
#pragma unroll
            for (int mt = 0; mt < 4; mt++) {
                unsigned ah[4], alr[4];
                int arow = wm * 64 + mt * 16 + g1 * 8 + li;
                int acol = ks * 16 + g2 * 8;
                unsigned ad = smem_u32(&Ah[arow * AKP + acol]);
                LDSM_X4(ah, ad);
                ad = smem_u32(&Al[arow * AKP + acol]);
                LDSM_X4(alr, ad);
#pragma unroll
                for (int nt = 0; nt < 4; nt++) {
                    MMA16816(acc[mt][nt], ah, bh[2 * nt], bh[2 * nt + 1]);
                    MMA16816(acc[mt][nt], ah, bl[2 * nt], bl[2 * nt + 1]);
                    MMA16816(acc[mt][nt], alr, bh[2 * nt], bh[2 * nt + 1]);
                }
            }
        }
        __syncthreads();
    }

    // ---- epilogue: c-frag layout r=lane>>2, c=2*(lane&3) ----
    const int cr  = lane >> 2;
    const int cc2 = (lane & 3) << 1;
#pragma unroll
    for (int mt = 0; mt < 4; mt++)
#pragma unroll
        for (int nt = 0; nt < 4; nt++) {
            int r = bm + wm * 64 + mt * 16 + cr;
            int c = bn + wn * 32 + nt * 8 + cc2;
            *(float2*)&C[(size_t)r * N + c]       = make_float2(acc[mt][nt][0], acc[mt][nt][1]);
            *(float2*)&C[(size_t)(r + 8) * N + c] = make_float2(acc[mt][nt][2], acc[mt][nt][3]);
        }
}

// ---------------- QKV epilogue: gate+ve add, RoPE + RMS on q,k --------------
__global__ __launch_bounds__(256) void qkv_epilogue(
    float* __restrict__ q, float* __restrict__ k, float* __restrict__ v,
    const float* __restrict__ x, const float* __restrict__ ve,
    const float* __restrict__ cosb, const float* __restrict__ sinb,
    const float* __restrict__ Wgate)
{
    const int token = blockIdx.x;
    const int t     = token & (TT - 1);
    const int tid   = threadIdx.x;

    __shared__ float gate[NKV];
    if (tid < NKV) {
        float s = 0.f;
        const float* xp = x + (size_t)token * CC;
#pragma unroll
        for (int g = 0; g < GC; g++) s += xp[g] * Wgate[g * NKV + tid];
        gate[tid] = 2.f / (1.f + expf(-s));
    }
    __syncthreads();

    {   // v = v + gate * ve
        float* vp        = v  + (size_t)token * (NKV * HD);
        const float* vep = ve + (size_t)token * (NKV * HD);
        for (int i = tid; i < NKV * HD; i += 256)
            vp[i] += gate[i >> 7] * vep[i];
    }

    const int warp = tid >> 5, lane = tid & 31;
    const float* cp = cosb + (size_t)t * (HD / 2);
    const float* sp = sinb + (size_t)t * (HD / 2);
    for (int h = warp; h < NH + NKV; h += 8) {
        float* base = (h < NH) ? (q + (size_t)token * (NH * HD) + h * HD)
                               : (k + (size_t)token * (NKV * HD) + (h - NH) * HD);
        float t1a = base[lane],      t2a = base[lane + 64];
        float t1b = base[lane + 32], t2b = base[lane + 96];
        float ca = cp[lane],      sa = sp[lane];
        float cb = cp[lane + 32], sb = sp[lane + 32];
        float o0 =  t1a * ca + t2a * sa;
        float o1 = -t1a * sa + t2a * ca;
        float o2 =  t1b * cb + t2b * sb;
        float o3 = -t1b * sb + t2b * cb;
        float ss = o0 * o0 + o1 * o1 + o2 * o2 + o3 * o3;
#pragma unroll
        for (int off = 16; off; off >>= 1)
            ss += __shfl_xor_sync(0xffffffffu, ss, off);
        float sc = rsqrtf(ss * (1.f / HD) + 1.19209290e-07f);
        base[lane]      = o0 * sc;
        base[lane + 64] = o1 * sc;
        base[lane + 32] = o2 * sc;
        base[lane + 96] = o3 * sc;
    }
}

// ---------------- Flash attention (fp32 SIMT, online softmax) ---------------
__global__ __launch_bounds__(256) void attn_kernel(
    const float* __restrict__ q, const float* __restrict__ k,
    const float* __restrict__ v, float* __restrict__ y)
{
    extern __shared__ float sm[];
    float* Qs = sm;                   // BR * KP
    float* Ks = Qs + BR * KP;         // BC * KP
    float* Vs = Ks + BC * KP;         // BC * KP

    const int q0   = blockIdx.x * BR;
    const int h    = blockIdx.y;
    const int b    = blockIdx.z;
    const int hk   = h >> 2;          // NH/NKV = 4
    const int tid  = threadIdx.x;
    const int warp = tid >> 5, lane = tid & 31;

    const float qscale = 0.08838834764831845f;  // 1/sqrt(HD)

    for (int i = tid; i < BR * (HD / 4); i += 256) {
        int r  = i >> 5;
        int dq = (i & 31) << 2;
        float4 qv = *(const float4*)(q + ((size_t)(b * TT + q0 + r) * NH + h) * HD + dq);
        qv.x *= qscale; qv.y *= qscale; qv.z *= qscale; qv.w *= qscale;
        *(float4*)&Qs[r * KP + dq] = qv;
    }

    const int r0 = warp * 8;
    float m[8], l[8], acc[8][4];
#pragma unroll
    for (int r = 0; r < 8; r++) {
        m[r] = -CUDART_INF_F; l[r] = 0.f;
        acc[r][0] = acc[r][1] = acc[r][2] = acc[r][3] = 0.f;
    }

    const int ntiles = (q0 + BR) / BC;
    for (int jt = 0; jt < ntiles; jt++) {
        __syncthreads();   // K/V reuse guard (iter 0: also orders Q load)
        for (int i = tid; i < BC * (HD / 4); i += 256) {
            int r  = i >> 5;
            int dq = (i & 31) << 2;
            int kk = jt * BC + r;
            const size_t g = ((size_t)(b * TT + kk) * NKV + hk) * HD + dq;
            *(float4*)&Ks[r * KP + dq] = *(const float4*)(k + g);
            *(float4*)&Vs[r * KP + dq] = *(const float4*)(v + g);
        }
        __syncthreads();

        float s[8];
#pragma unroll
        for (int r = 0; r < 8; r++) s[r] = 0.f;
#pragma unroll 8
        for (int d = 0; d < HD; d += 4) {
            float4 kv = *(float4*)&Ks[lane * KP + d];
#pragma unroll
            for (int r = 0; r < 8; r++) {
                float4 qv = *(float4*)&Qs[(r0 + r) * KP + d];
                s[r] += qv.x * kv.x + qv.y * kv.y + qv.z * kv.z + qv.w * kv.w;
            }
        }

        const int kcol = jt * BC + lane;
#pragma unroll
        for (int r = 0; r < 8; r++) {
            const int qrow = q0 + r0 + r;
            float sv = (kcol <= qrow) ? s[r] : -CUDART_INF_F;
            float mt = sv;
#pragma unroll
            for (int off = 16; off; off >>= 1)
                mt = fmaxf(mt, __shfl_xor_sync(0xffffffffu, mt, off));
            float mnew  = fmaxf(m[r], mt);
            float alpha = __expf(m[r] - mnew);
            float p     = __expf(sv - mnew);
            float lt = p;
#pragma unroll
            for (int off = 16; off; off >>= 1)
                lt += __shfl_xor_sync(0xffffffffu, lt, off);
            l[r] = l[r] * alpha + lt;
            m[r] = mnew;
            acc[r][0] *= alpha; acc[r][1] *= alpha;
            acc[r][2] *= alpha; acc[r][3] *= alpha;
            s[r] = p;
        }

#pragma unroll
        for (int j = 0; j < BC; j++) {
            float4 vv = *(float4*)&Vs[j * KP + (lane << 2)];
#pragma unroll
            for (int r = 0; r < 8; r++) {
                float pj = __shfl_sync(0xffffffffu, s[r], j);
                acc[r][0] += pj * vv.x;
                acc[r][1] += pj * vv.y;
                acc[r][2] += pj * vv.z;
                acc[r][3] += pj * vv.w;
            }
        }
    }

#pragma unroll
    for (int r = 0; r < 8; r++) {
        float inv = 1.f / l[r];
        float4 o = make_float4(acc[r][0] * inv, acc[r][1] * inv,
                               acc[r][2] * inv, acc[r][3] * inv);
        *(float4*)(y + (size_t)(b * TT + q0 + r0 + r) * CC + h * HD + (lane << 2)) = o;
    }
}

// ---------------- launch ----------------------------------------------------
extern "C" void kernel_launch(void* const* d_in, const int* in_sizes, int n_in,
                              void* d_out, int out_size)
{
    const float* x     = (const float*)d_in[0];
    const float* ve    = (const float*)d_in[1];
    const float* cosb  = (const float*)d_in[2];
    const float* sinb  = (const float*)d_in[3];
    const float* Wq    = (const float*)d_in[4];
    const float* Wk    = (const float*)d_in[5];
    const float* Wv    = (const float*)d_in[6];
    const float* Wproj = (const float*)d_in[7];
    const float* Wgate = (const float*)d_in[8];
    float* out = (float*)d_out;

    float *qb, *kb, *vb, *yb;
    cudaGetSymbolAddress((void**)&qb, g_q);
    cudaGetSymbolAddress((void**)&kb, g_k);
    cudaGetSymbolAddress((void**)&vb, g_v);
    cudaGetSymbolAddress((void**)&yb, g_y);

    dim3 blk(256);
    gemm_bf16x3<<<dim3((NH * HD) / GBN, MTOK / GBM), blk>>>(x, Wq, qb, MTOK, NH * HD, CC);
    gemm_bf16x3<<<dim3((NKV * HD) / GBN, MTOK / GBM), blk>>>(x, Wk, kb, MTOK, NKV * HD, CC);
    gemm_bf16x3<<<dim3((NKV * HD) / GBN, MTOK / GBM), blk>>>(x, Wv, vb, MTOK, NKV * HD, CC);

    qkv_epilogue<<<MTOK, 256>>>(qb, kb, vb, x, ve, cosb, sinb, Wgate);

    const int smem = (BR * KP + 2 * BC * KP) * (int)sizeof(float);
    cudaFuncSetAttribute(attn_kernel, cudaFuncAttributeMaxDynamicSharedMemorySize, smem);
    attn_kernel<<<dim3(TT / BR, NH, BB), 256, smem>>>(qb, kb, vb, yb);

    gemm_bf16x3<<<dim3(CC / GBN, MTOK / GBM), blk>>>(yb, Wproj, out, MTOK, CC, CC);
}

// round 6
// speedup vs baseline: 2.9829x; 1.8703x over previous
#include <cuda_runtime.h>
#include <cuda_bf16.h>
#include <math_constants.h>

#define BB   2
#define TT   2048
#define CC   2048
#define NH   16
#define NKV  4
#define HD   128
#define GC   32
#define MTOK (BB*TT)

// ---------------- scratch (device globals: no allocations allowed) ----------
__device__ float g_q[(size_t)MTOK*NH*HD];
__device__ float g_k[(size_t)MTOK*NKV*HD];
__device__ float g_v[(size_t)MTOK*NKV*HD];
__device__ float g_y[(size_t)MTOK*CC];

// ======================= shared helpers =====================================
__device__ __forceinline__ unsigned smem_u32(const void* p) {
    return (unsigned)__cvta_generic_to_shared(p);
}
__device__ __forceinline__ void bsplit(float f, __nv_bfloat16& h, __nv_bfloat16& l) {
    h = __float2bfloat16(f);
    l = __float2bfloat16(f - __bfloat162float(h));
}
__device__ __forceinline__ void split_store4(__nv_bfloat16* Hh, __nv_bfloat16* Hl,
                                             int o, float4 v) {
    __nv_bfloat16 h0, l0, h1, l1, h2, l2, h3, l3;
    bsplit(v.x, h0, l0); bsplit(v.y, h1, l1);
    bsplit(v.z, h2, l2); bsplit(v.w, h3, l3);
    *(__nv_bfloat162*)&Hh[o]     = __halves2bfloat162(h0, h1);
    *(__nv_bfloat162*)&Hh[o + 2] = __halves2bfloat162(h2, h3);
    *(__nv_bfloat162*)&Hl[o]     = __halves2bfloat162(l0, l1);
    *(__nv_bfloat162*)&Hl[o + 2] = __halves2bfloat162(l2, l3);
}

#define MMA16816(d, a, b0v, b1v)                                              \
    asm volatile("mma.sync.aligned.m16n8k16.row.col.f32.bf16.bf16.f32 "       \
                 "{%0,%1,%2,%3}, {%4,%5,%6,%7}, {%8,%9}, {%0,%1,%2,%3};"      \
                 : "+f"(d[0]), "+f"(d[1]), "+f"(d[2]), "+f"(d[3])             \
                 : "r"(a[0]), "r"(a[1]), "r"(a[2]), "r"(a[3]),                \
                   "r"(b0v), "r"(b1v))

#define LDSM_X4(r, addr)                                                      \
    asm volatile("ldmatrix.sync.aligned.m8n8.x4.shared.b16 {%0,%1,%2,%3}, [%4];" \
                 : "=r"(r[0]), "=r"(r[1]), "=r"(r[2]), "=r"(r[3]) : "r"(addr))

#define LDSM_X4T(r0, r1, r2, r3, addr)                                        \
    asm volatile("ldmatrix.sync.aligned.m8n8.x4.trans.shared.b16 {%0,%1,%2,%3}, [%4];" \
                 : "=r"(r0), "=r"(r1), "=r"(r2), "=r"(r3) : "r"(addr))

// ======================= bf16x3 tensor-core GEMM ============================
#define GBM 128
#define GBN 128
#define GBK 32
#define AKP 40
#define BNP 136

__global__ __launch_bounds__(256) void gemm_bf16x3(
    const float* __restrict__ A, const float* __restrict__ B,
    float* __restrict__ C, int M, int N, int K)
{
    __shared__ __nv_bfloat16 Ah[GBM * AKP], Al[GBM * AKP];
    __shared__ __nv_bfloat16 Bh[GBK * BNP], Bl[GBK * BNP];

    const int tid  = threadIdx.x;
    const int lane = tid & 31, warp = tid >> 5;
    const int wm   = warp >> 2, wn = warp & 3;
    const int bm   = blockIdx.y * GBM, bn = blockIdx.x * GBN;
    const int li   = lane & 7;
    const int g1   = (lane >> 3) & 1;
    const int g2   = lane >> 4;

    float acc[4][4][4];
#pragma unroll
    for (int mt = 0; mt < 4; mt++)
#pragma unroll
        for (int nt = 0; nt < 4; nt++)
#pragma unroll
            for (int i = 0; i < 4; i++) acc[mt][nt][i] = 0.f;

    const int arow_l = tid >> 3;
    const int acol_l = (tid & 7) << 2;
    const int brow_l = tid >> 5;
    const int bcol_l = lane << 2;

    for (int k0 = 0; k0 < K; k0 += GBK) {
#pragma unroll
        for (int p = 0; p < 4; p++) {
            int r = arow_l + 32 * p;
            float4 v = *(const float4*)(A + (size_t)(bm + r) * K + k0 + acol_l);
            split_store4(Ah, Al, r * AKP + acol_l, v);
        }
#pragma unroll
        for (int p = 0; p < 4; p++) {
            int kr = brow_l + 8 * p;
            float4 v = *(const float4*)(B + (size_t)(k0 + kr) * N + bn + bcol_l);
            split_store4(Bh, Bl, kr * BNP + bcol_l, v);
        }
        __syncthreads();

#pragma unroll
        for (int ks = 0; ks < 2; ks++) {
            unsigned bh[8], bl[8];
#pragma unroll
            for (int pr = 0; pr < 2; pr++) {
                int krow = ks * 16 + g1 * 8 + li;
                int ncol = wn * 32 + pr * 16 + g2 * 8;
                unsigned ad = smem_u32(&Bh[krow * BNP + ncol]);
                LDSM_X4T(bh[4 * pr], bh[4 * pr + 1], bh[4 * pr + 2], bh[4 * pr + 3], ad);
                ad = smem_u32(&Bl[krow * BNP + ncol]);
                LDSM_X4T(bl[4 * pr], bl[4 * pr + 1], bl[4 * pr + 2], bl[4 * pr + 3], ad);
            }
#pragma unroll
            for (int mt = 0; mt < 4; mt++) {
                unsigned ah[4], alr[4];
                int arow = wm * 64 + mt * 16 + g1 * 8 + li;
                int acol = ks * 16 + g2 * 8;
                unsigned ad = smem_u32(&Ah[arow * AKP + acol]);
                LDSM_X4(ah, ad);
                ad = smem_u32(&Al[arow * AKP + acol]);
                LDSM_X4(alr, ad);
#pragma unroll
                for (int nt = 0; nt < 4; nt++) {
                    MMA16816(acc[mt][nt], ah, bh[2 * nt], bh[2 * nt + 1]);
                    MMA16816(acc[mt][nt], ah, bl[2 * nt], bl[2 * nt + 1]);
                    MMA16816(acc[mt][nt], alr, bh[2 * nt], bh[2 * nt + 1]);
                }
            }
        }
        __syncthreads();
    }

    const int cr  = lane >> 2;
    const int cc2 = (lane & 3) << 1;
#pragma unroll
    for (int mt = 0; mt < 4; mt++)
#pragma unroll
        for (int nt = 0; nt < 4; nt++) {
            int r = bm + wm * 64 + mt * 16 + cr;
            int c = bn + wn * 32 + nt * 8 + cc2;
            *(float2*)&C[(size_t)r * N + c]       = make_float2(acc[mt][nt][0], acc[mt][nt][1]);
            *(float2*)&C[(size_t)(r + 8) * N + c] = make_float2(acc[mt][nt][2], acc[mt][nt][3]);
        }
}

// ---------------- QKV epilogue: gate+ve add, RoPE + RMS on q,k --------------
__global__ __launch_bounds__(256) void qkv_epilogue(
    float* __restrict__ q, float* __restrict__ k, float* __restrict__ v,
    const float* __restrict__ x, const float* __restrict__ ve,
    const float* __restrict__ cosb, const float* __restrict__ sinb,
    const float* __restrict__ Wgate)
{
    const int token = blockIdx.x;
    const int t     = token & (TT - 1);
    const int tid   = threadIdx.x;

    __shared__ float gate[NKV];
    if (tid < NKV) {
        float s = 0.f;
        const float* xp = x + (size_t)token * CC;
#pragma unroll
        for (int g = 0; g < GC; g++) s += xp[g] * Wgate[g * NKV + tid];
        gate[tid] = 2.f / (1.f + expf(-s));
    }
    __syncthreads();

    {
        float* vp        = v  + (size_t)token * (NKV * HD);
        const float* vep = ve + (size_t)token * (NKV * HD);
        for (int i = tid; i < NKV * HD; i += 256)
            vp[i] += gate[i >> 7] * vep[i];
    }

    const int warp = tid >> 5, lane = tid & 31;
    const float* cp = cosb + (size_t)t * (HD / 2);
    const float* sp = sinb + (size_t)t * (HD / 2);
    for (int h = warp; h < NH + NKV; h += 8) {
        float* base = (h < NH) ? (q + (size_t)token * (NH * HD) + h * HD)
                               : (k + (size_t)token * (NKV * HD) + (h - NH) * HD);
        float t1a = base[lane],      t2a = base[lane + 64];
        float t1b = base[lane + 32], t2b = base[lane + 96];
        float ca = cp[lane],      sa = sp[lane];
        float cb = cp[lane + 32], sb = sp[lane + 32];
        float o0 =  t1a * ca + t2a * sa;
        float o1 = -t1a * sa + t2a * ca;
        float o2 =  t1b * cb + t2b * sb;
        float o3 = -t1b * sb + t2b * cb;
        float ss = o0 * o0 + o1 * o1 + o2 * o2 + o3 * o3;
#pragma unroll
        for (int off = 16; off; off >>= 1)
            ss += __shfl_xor_sync(0xffffffffu, ss, off);
        float sc = rsqrtf(ss * (1.f / HD) + 1.19209290e-07f);
        base[lane]      = o0 * sc;
        base[lane + 64] = o1 * sc;
        base[lane + 32] = o2 * sc;
        base[lane + 96] = o3 * sc;
    }
}

// ============= tensor-core flash attention (bf16x3 split) ===================
#define AB  128
#define AC  64
#define SKP 136

__global__ __launch_bounds__(256) void attn_tc(
    const float* __restrict__ q, const float* __restrict__ k,
    const float* __restrict__ v, float* __restrict__ y)
{
    extern __shared__ __nv_bfloat16 smb[];
    __nv_bfloat16* Qh = smb;
    __nv_bfloat16* Ql = Qh + AB * SKP;
    __nv_bfloat16* Kh = Ql + AB * SKP;
    __nv_bfloat16* Kl = Kh + AC * SKP;
    __nv_bfloat16* Vh = Kl + AC * SKP;
    __nv_bfloat16* Vl = Vh + AC * SKP;

    const int q0   = blockIdx.x * AB;
    const int h    = blockIdx.y, b = blockIdx.z;
    const int hk   = h >> 2;
    const int tid  = threadIdx.x, lane = tid & 31, warp = tid >> 5;
    const int li   = lane & 7;
    const int g1   = (lane >> 3) & 1;
    const int g2   = lane >> 4;
    const int sel  = lane >> 3;
    const int kna  = (sel & 2) ? 8 : 0;
    const int kka  = (sel & 1) ? 8 : 0;
    const float qscale = 0.08838834764831845f;  // 1/sqrt(HD)

    for (int i = tid; i < AB * 32; i += 256) {
        int r = i >> 5, c = (i & 31) << 2;
        float4 qv = *(const float4*)(q + ((size_t)(b * TT + q0 + r) * NH + h) * HD + c);
        qv.x *= qscale; qv.y *= qscale; qv.z *= qscale; qv.w *= qscale;
        split_store4(Qh, Ql, r * SKP + c, qv);
    }

    float o[16][4];
#pragma unroll
    for (int dn = 0; dn < 16; dn++)
#pragma unroll
        for (int i = 0; i < 4; i++) o[dn][i] = 0.f;
    float mrow[2] = {-CUDART_INF_F, -CUDART_INF_F};
    float lrow[2] = {0.f, 0.f};

    const int wr_lo  = q0 + warp * 16;
    const int wr_top = wr_lo + 15;
    const int rA     = wr_lo + (lane >> 2);
    const int ntiles = (q0 + AB) / AC;

    for (int jt = 0; jt < ntiles; jt++) {
        __syncthreads();
        for (int i = tid; i < AC * 32; i += 256) {
            int r = i >> 5, c = (i & 31) << 2;
            const size_t g = ((size_t)(b * TT + jt * AC + r) * NKV + hk) * HD + c;
            split_store4(Kh, Kl, r * SKP + c, *(const float4*)(k + g));
            split_store4(Vh, Vl, r * SKP + c, *(const float4*)(v + g));
        }
        __syncthreads();

        const int kt0 = jt * AC;
        if (kt0 > wr_top) continue;

        float s[8][4];
#pragma unroll
        for (int nt = 0; nt < 8; nt++)
#pragma unroll
            for (int i = 0; i < 4; i++) s[nt][i] = 0.f;

#pragma unroll
        for (int kc = 0; kc < 8; kc++) {
            unsigned qh_[4], ql_[4];
            {
                unsigned ad = smem_u32(&Qh[(warp * 16 + g1 * 8 + li) * SKP + kc * 16 + g2 * 8]);
                LDSM_X4(qh_, ad);
                ad = smem_u32(&Ql[(warp * 16 + g1 * 8 + li) * SKP + kc * 16 + g2 * 8]);
                LDSM_X4(ql_, ad);
            }
#pragma unroll
            for (int np = 0; np < 4; np++) {
                unsigned kh_[4], kl_[4];
                unsigned ad = smem_u32(&Kh[(np * 16 + kna + li) * SKP + kc * 16 + kka]);
                LDSM_X4(kh_, ad);
                ad = smem_u32(&Kl[(np * 16 + kna + li) * SKP + kc * 16 + kka]);
                LDSM_X4(kl_, ad);
                MMA16816(s[2 * np],     qh_, kh_[0], kh_[1]);
                MMA16816(s[2 * np],     qh_, kl_[0], kl_[1]);
                MMA16816(s[2 * np],     ql_, kh_[0], kh_[1]);
                MMA16816(s[2 * np + 1], qh_, kh_[2], kh_[3]);
                MMA16816(s[2 * np + 1], qh_, kl_[2], kl_[3]);
                MMA16816(s[2 * np + 1], ql_, kh_[2], kh_[3]);
            }
        }

        if (kt0 + AC - 1 > wr_lo) {
#pragma unroll
            for (int nt = 0; nt < 8; nt++) {
                int c0 = kt0 + nt * 8 + ((lane & 3) << 1);
                if (c0 > rA)         s[nt][0] = -CUDART_INF_F;
                if (c0 + 1 > rA)     s[nt][1] = -CUDART_INF_F;
                if (c0 > rA + 8)     s[nt][2] = -CUDART_INF_F;
                if (c0 + 1 > rA + 8) s[nt][3] = -CUDART_INF_F;
            }
        }

        float mt0 = -CUDART_INF_F, mt1 = -CUDART_INF_F;
#pragma unroll
        for (int nt = 0; nt < 8; nt++) {
            mt0 = fmaxf(mt0, fmaxf(s[nt][0], s[nt][1]));
            mt1 = fmaxf(mt1, fmaxf(s[nt][2], s[nt][3]));
        }
        mt0 = fmaxf(mt0, __shfl_xor_sync(0xffffffffu, mt0, 1));
        mt0 = fmaxf(mt0, __shfl_xor_sync(0xffffffffu, mt0, 2));
        mt1 = fmaxf(mt1, __shfl_xor_sync(0xffffffffu, mt1, 1));
        mt1 = fmaxf(mt1, __shfl_xor_sync(0xffffffffu, mt1, 2));
        float mn0 = fmaxf(mrow[0], mt0);
        float mn1 = fmaxf(mrow[1], mt1);
        float a0 = __expf(mrow[0] - mn0);
        float a1 = __expf(mrow[1] - mn1);
        mrow[0] = mn0; mrow[1] = mn1;

        unsigned Phr[8][2], Plr[8][2];
        float ls0 = 0.f, ls1 = 0.f;
#pragma unroll
        for (int nt = 0; nt < 8; nt++) {
            float p0 = __expf(s[nt][0] - mn0);
            float p1 = __expf(s[nt][1] - mn0);
            float p2 = __expf(s[nt][2] - mn1);
            float p3 = __expf(s[nt][3] - mn1);
            ls0 += p0 + p1;
            ls1 += p2 + p3;
            __nv_bfloat16 h0, l0, h1, l1, h2, l2, h3, l3;
            bsplit(p0, h0, l0); bsplit(p1, h1, l1);
            bsplit(p2, h2, l2); bsplit(p3, h3, l3);
            __nv_bfloat162 t;
            t = __halves2bfloat162(h0, h1); Phr[nt][0] = *(unsigned*)&t;
            t = __halves2bfloat162(h2, h3); Phr[nt][1] = *(unsigned*)&t;
            t = __halves2bfloat162(l0, l1); Plr[nt][0] = *(unsigned*)&t;
            t = __halves2bfloat162(l2, l3); Plr[nt][1] = *(unsigned*)&t;
        }
        ls0 += __shfl_xor_sync(0xffffffffu, ls0, 1);
        ls0 += __shfl_xor_sync(0xffffffffu, ls0, 2);
        ls1 += __shfl_xor_sync(0xffffffffu, ls1, 1);
        ls1 += __shfl_xor_sync(0xffffffffu, ls1, 2);
        lrow[0] = lrow[0] * a0 + ls0;
        lrow[1] = lrow[1] * a1 + ls1;
#pragma unroll
        for (int dn = 0; dn < 16; dn++) {
            o[dn][0] *= a0; o[dn][1] *= a0;
            o[dn][2] *= a1; o[dn][3] *= a1;
        }

#pragma unroll
        for (int kc2 = 0; kc2 < 4; kc2++) {
            unsigned pah[4] = {Phr[2 * kc2][0], Phr[2 * kc2][1],
                               Phr[2 * kc2 + 1][0], Phr[2 * kc2 + 1][1]};
            unsigned pal[4] = {Plr[2 * kc2][0], Plr[2 * kc2][1],
                               Plr[2 * kc2 + 1][0], Plr[2 * kc2 + 1][1]};
#pragma unroll
            for (int dn = 0; dn < 8; dn++) {
                unsigned vh_[4], vl_[4];
                unsigned ad = smem_u32(&Vh[(kc2 * 16 + g1 * 8 + li) * SKP + dn * 16 + g2 * 8]);
                LDSM_X4T(vh_[0], vh_[1], vh_[2], vh_[3], ad);
                ad = smem_u32(&Vl[(kc2 * 16 + g1 * 8 + li) * SKP + dn * 16 + g2 * 8]);
                LDSM_X4T(vl_[0], vl_[1], vl_[2], vl_[3], ad);
                MMA16816(o[2 * dn],     pah, vh_[0], vh_[1]);
                MMA16816(o[2 * dn],     pah, vl_[0], vl_[1]);
                MMA16816(o[2 * dn],     pal, vh_[0], vh_[1]);
                MMA16816(o[2 * dn + 1], pah, vh_[2], vh_[3]);
                MMA16816(o[2 * dn + 1], pah, vl_[2], vl_[3]);
                MMA16816(o[2 * dn + 1], pal, vh_[2], vh_[3]);
            }
        }
    }

    float inv0 = 1.f / lrow[0];
    float inv1 = 1.f / lrow[1];
    const int cbase = (lane & 3) << 1;
#pragma unroll
    for (int dn = 0; dn < 16; dn++) {
        int c = h * HD + dn * 8 + cbase;
        *(float2*)&y[(size_t)(b * TT + rA) * CC + c] =
            make_float2(o[dn][0] * inv0, o[dn][1] * inv0);
        *(float2*)&y[(size_t)(b * TT + rA + 8) * CC + c] =
            make_float2(o[dn][2] * inv1, o[dn][3] * inv1);
    }
}

// ---------------- launch ----------------------------------------------------
extern "C" void kernel_launch(void* const* d_in, const int* in_sizes, int n_in,
                              void* d_out, int out_size)
{
    const float* x     = (const float*)d_in[0];
    const float* ve    = (const float*)d_in[1];
    const float* cosb  = (const float*)d_in[2];
    const float* sinb  = (const float*)d_in[3];
    const float* Wq    = (const float*)d_in[4];
    const float* Wk    = (const float*)d_in[5];
    const float* Wv    = (const float*)d_in[6];
    const float* Wproj = (const float*)d_in[7];
    const float* Wgate = (const float*)d_in[8];
    float* out = (float*)d_out;

    float *qb, *kb, *vb, *yb;
    cudaGetSymbolAddress((void**)&qb, g_q);
    cudaGetSymbolAddress((void**)&kb, g_k);
    cudaGetSymbolAddress((void**)&vb, g_v);
    cudaGetSymbolAddress((void**)&yb, g_y);

    dim3 blk(256);
    gemm_bf16x3<<<dim3((NH * HD) / GBN, MTOK / GBM), blk>>>(x, Wq, qb, MTOK, NH * HD, CC);
    gemm_bf16x3<<<dim3((NKV * HD) / GBN, MTOK / GBM), blk>>>(x, Wk, kb, MTOK, NKV * HD, CC);
    gemm_bf16x3<<<dim3((NKV * HD) / GBN, MTOK / GBM), blk>>>(x, Wv, vb, MTOK, NKV * HD, CC);

    qkv_epilogue<<<MTOK, 256>>>(qb, kb, vb, x, ve, cosb, sinb, Wgate);

    const int asmem = (2 * AB * SKP + 4 * AC * SKP) * (int)sizeof(__nv_bfloat16);
    cudaFuncSetAttribute(attn_tc, cudaFuncAttributeMaxDynamicSharedMemorySize, asmem);
    attn_tc<<<dim3(TT / AB, NH, BB), 256, asmem>>>(qb, kb, vb, yb);

    gemm_bf16x3<<<dim3(CC / GBN, MTOK / GBM), blk>>>(yb, Wproj, out, MTOK, CC, CC);
}